// round 6
// baseline (speedup 1.0000x reference)
#include <cuda_runtime.h>
#include <cuda_fp16.h>
#include <math.h>
#include <stdint.h>

// ----------------------------------------------------------------------------
// Causal masked softmax attention. N=64, T=1024, D=64.  (v2 resubmit: renamed
// symbol to bust any source-hash-keyed build cache; no functional change.)
// QK^T on tf32 m16n8k8 (precision), PV on fp16 m16n8k16 with P held in
// registers (tf32-C layout == fp16-A layout). V transposed fp16 in shared.
// Q staged through the K buffer; 26.3 KB smem -> 4 blocks/SM.
// ----------------------------------------------------------------------------

namespace {
constexpr int kT = 1024;
constexpr int kD = 64;
constexpr int BM = 64;
constexpr int BN = 64;
constexpr int THREADS = 128;
constexpr int STRK = 68;    // sK float stride: B-load bank (4g+tig) bijective
constexpr int STRVT2 = 36;  // sVT half2 stride: bank (4g+8t+tig) bijective
constexpr float kQScale = 0.18033688011112042f;  // (1/8) * log2(e)
constexpr float kPad = -1e30f;                   // exp2 -> exactly 0
constexpr int SM_K = 0;                          // floats
constexpr int SM_VT = BN * STRK;                 // sVT as half2 (word units)
constexpr int SM_F = SM_VT + kD * STRVT2;
constexpr int SMEM_WORDS = SM_F + BN;            // ~26.3 KB
}  // namespace

__device__ __forceinline__ float ex2f(float x) {
    float r; asm("ex2.approx.ftz.f32 %0, %1;" : "=f"(r) : "f"(x)); return r;
}
__device__ __forceinline__ float tf32r(float x) {
    uint32_t u; asm("cvt.rna.tf32.f32 %0, %1;" : "=r"(u) : "f"(x));
    return __uint_as_float(u);
}
__device__ __forceinline__ uint32_t f2h2(float lo, float hi) {
    __half2 h = __floats2half2_rn(lo, hi);
    return *reinterpret_cast<uint32_t*>(&h);
}
__device__ __forceinline__ void mma_tf32(float (&d)[4],
                                         uint32_t a0, uint32_t a1,
                                         uint32_t a2, uint32_t a3,
                                         uint32_t b0, uint32_t b1) {
    asm volatile(
        "mma.sync.aligned.m16n8k8.row.col.f32.tf32.tf32.f32 "
        "{%0,%1,%2,%3}, {%4,%5,%6,%7}, {%8,%9}, {%0,%1,%2,%3};\n"
        : "+f"(d[0]), "+f"(d[1]), "+f"(d[2]), "+f"(d[3])
        : "r"(a0), "r"(a1), "r"(a2), "r"(a3), "r"(b0), "r"(b1));
}
__device__ __forceinline__ void mma_f16(float (&d)[4],
                                        uint32_t a0, uint32_t a1,
                                        uint32_t a2, uint32_t a3,
                                        uint32_t b0, uint32_t b1) {
    asm volatile(
        "mma.sync.aligned.m16n8k16.row.col.f32.f16.f16.f32 "
        "{%0,%1,%2,%3}, {%4,%5,%6,%7}, {%8,%9}, {%0,%1,%2,%3};\n"
        : "+f"(d[0]), "+f"(d[1]), "+f"(d[2]), "+f"(d[3])
        : "r"(a0), "r"(a1), "r"(a2), "r"(a3), "r"(b0), "r"(b1));
}

__global__ __launch_bounds__(THREADS, 4)
void attn_mixed_v2_kernel(const float* __restrict__ Q,
                          const float* __restrict__ K,
                          const float* __restrict__ V,
                          float* __restrict__ O) {
    extern __shared__ float sm[];
    float* sK = sm + SM_K;                            // [BN][STRK] tf32 keys
    uint32_t* sVT = (uint32_t*)(sm + SM_VT);          // [kD][STRVT2] half2 V^T
    float* sF = sm + SM_F;                            // [BN] |K| row sums

    const int tid = threadIdx.x;
    const int warp = tid >> 5;
    const int lane = tid & 31;
    const int g = lane >> 2;     // 0..7
    const int tig = lane & 3;    // 0..3
    const int qt = (kT / BM - 1) - blockIdx.x;   // heavy q-tiles first
    const int bn = blockIdx.y;
    const int q0 = qt * BM;

    const float* Qg = Q + ((size_t)bn * kT + q0) * kD;
    const float* Kg = K + (size_t)bn * kT * kD;
    const float* Vg = V + (size_t)bn * kT * kD;

    const int tx = tid & 15, ty = tid >> 4;      // 16x8 loader layout

    // ---- stage Q (scaled, tf32) through the sK buffer -----------------------
#pragma unroll
    for (int i = 0; i < 8; i++) {
        const int r = ty + 8 * i;
        float4 qv = *(const float4*)(Qg + r * kD + 4 * tx);
        float* dst = sK + r * STRK + 4 * tx;
        dst[0] = tf32r(qv.x * kQScale);
        dst[1] = tf32r(qv.y * kQScale);
        dst[2] = tf32r(qv.z * kQScale);
        dst[3] = tf32r(qv.w * kQScale);
    }
    __syncthreads();

    // ---- Q fragments: register-resident for the whole kernel ----------------
    uint32_t qf[8][4];
    {
        const float* mq = sK + (warp * 16) * STRK;
#pragma unroll
        for (int kb = 0; kb < 8; kb++) {
            qf[kb][0] = __float_as_uint(mq[g * STRK + kb * 8 + tig]);
            qf[kb][1] = __float_as_uint(mq[(g + 8) * STRK + kb * 8 + tig]);
            qf[kb][2] = __float_as_uint(mq[g * STRK + kb * 8 + tig + 4]);
            qf[kb][3] = __float_as_uint(mq[(g + 8) * STRK + kb * 8 + tig + 4]);
        }
    }

    float m0 = kPad, m1 = kPad, l0 = 0.f, l1 = 0.f;
    float o[8][4];
#pragma unroll
    for (int nb = 0; nb < 8; nb++)
#pragma unroll
        for (int j = 0; j < 4; j++) o[nb][j] = 0.f;

    const int rowg0 = q0 + warp * 16 + g;
    const int rowg1 = rowg0 + 8;

    for (int kt = 0; kt <= qt; kt++) {
        const int k0 = kt * BN;
        __syncthreads();   // prior tile's MMAs done with sK/sVT (also fences Q staging)

        // ---- load K (tf32, row-major) + flags, V (fp16, transposed) ---------
#pragma unroll
        for (int i = 0; i < 8; i++) {
            const int r = ty + 8 * i;
            float4 kv = *(const float4*)(Kg + (size_t)(k0 + r) * kD + 4 * tx);
            float* dk = sK + r * STRK + 4 * tx;
            dk[0] = tf32r(kv.x); dk[1] = tf32r(kv.y);
            dk[2] = tf32r(kv.z); dk[3] = tf32r(kv.w);
            float asum = fabsf(kv.x) + fabsf(kv.y) + fabsf(kv.z) + fabsf(kv.w);
#pragma unroll
            for (int off = 8; off > 0; off >>= 1)
                asum += __shfl_xor_sync(0xffffffffu, asum, off, 16);
            if (tx == 0) sF[r] = asum;
            float4 vv = *(const float4*)(Vg + (size_t)(k0 + r) * kD + 4 * tx);
            __half* vt = (__half*)sVT;         // half-granular transpose store
            vt[(4 * tx + 0) * (2 * STRVT2) + r] = __float2half_rn(vv.x);
            vt[(4 * tx + 1) * (2 * STRVT2) + r] = __float2half_rn(vv.y);
            vt[(4 * tx + 2) * (2 * STRVT2) + r] = __float2half_rn(vv.z);
            vt[(4 * tx + 3) * (2 * STRVT2) + r] = __float2half_rn(vv.w);
        }
        __syncthreads();

        // ---- S = Q K^T (tf32 tensor cores) ----------------------------------
        float s[8][4];
#pragma unroll
        for (int nb = 0; nb < 8; nb++)
#pragma unroll
            for (int j = 0; j < 4; j++) s[nb][j] = 0.f;
#pragma unroll
        for (int kb = 0; kb < 8; kb++) {
#pragma unroll
            for (int nb = 0; nb < 8; nb++) {
                const float* kp = sK + (nb * 8 + g) * STRK + kb * 8 + tig;
                mma_tf32(s[nb], qf[kb][0], qf[kb][1], qf[kb][2], qf[kb][3],
                         __float_as_uint(kp[0]), __float_as_uint(kp[4]));
            }
        }

        // ---- masks ----------------------------------------------------------
        const bool diag = (kt == qt);
#pragma unroll
        for (int nb = 0; nb < 8; nb++) {
            const int c = k0 + nb * 8 + 2 * tig;
            const float f0 = sF[nb * 8 + 2 * tig];
            const float f1 = sF[nb * 8 + 2 * tig + 1];
            if (f0 == 0.f) { s[nb][0] = kPad; s[nb][2] = kPad; }
            if (f1 == 0.f) { s[nb][1] = kPad; s[nb][3] = kPad; }
            if (diag) {
                if (c > rowg0)     s[nb][0] = kPad;
                if (c + 1 > rowg0) s[nb][1] = kPad;
                if (c > rowg1)     s[nb][2] = kPad;
                if (c + 1 > rowg1) s[nb][3] = kPad;
            }
        }

        // ---- online softmax (base 2), p kept in registers -------------------
        float rmax0 = kPad, rmax1 = kPad;
#pragma unroll
        for (int nb = 0; nb < 8; nb++) {
            rmax0 = fmaxf(rmax0, fmaxf(s[nb][0], s[nb][1]));
            rmax1 = fmaxf(rmax1, fmaxf(s[nb][2], s[nb][3]));
        }
        rmax0 = fmaxf(rmax0, __shfl_xor_sync(0xffffffffu, rmax0, 1));
        rmax0 = fmaxf(rmax0, __shfl_xor_sync(0xffffffffu, rmax0, 2));
        rmax1 = fmaxf(rmax1, __shfl_xor_sync(0xffffffffu, rmax1, 1));
        rmax1 = fmaxf(rmax1, __shfl_xor_sync(0xffffffffu, rmax1, 2));
        const float mn0 = fmaxf(m0, rmax0);
        const float mn1 = fmaxf(m1, rmax1);
        const float corr0 = ex2f(m0 - mn0);
        const float corr1 = ex2f(m1 - mn1);
        float rs0 = 0.f, rs1 = 0.f;
#pragma unroll
        for (int nb = 0; nb < 8; nb++) {
            s[nb][0] = ex2f(s[nb][0] - mn0);
            s[nb][1] = ex2f(s[nb][1] - mn0);
            s[nb][2] = ex2f(s[nb][2] - mn1);
            s[nb][3] = ex2f(s[nb][3] - mn1);
            rs0 += s[nb][0] + s[nb][1];
            rs1 += s[nb][2] + s[nb][3];
        }
        rs0 += __shfl_xor_sync(0xffffffffu, rs0, 1);
        rs0 += __shfl_xor_sync(0xffffffffu, rs0, 2);
        rs1 += __shfl_xor_sync(0xffffffffu, rs1, 1);
        rs1 += __shfl_xor_sync(0xffffffffu, rs1, 2);
        l0 = l0 * corr0 + rs0; m0 = mn0;
        l1 = l1 * corr1 + rs1; m1 = mn1;
#pragma unroll
        for (int nb = 0; nb < 8; nb++) {
            o[nb][0] *= corr0; o[nb][1] *= corr0;
            o[nb][2] *= corr1; o[nb][3] *= corr1;
        }

        // ---- O += P V (fp16 tensor cores, P direct from S fragments) --------
        // tf32 m16n8k8 C layout == fp16 m16n8k16 A layout (half2-packed):
        //   a0 = (g, keys 2tig..2tig+1) of tile 2t  = pack(s[2t][0], s[2t][1])
        //   a1 = (g+8, same)                        = pack(s[2t][2], s[2t][3])
        //   a2/a3 = same rows, keys +8 (tile 2t+1)
#pragma unroll
        for (int t = 0; t < 4; t++) {      // 16-key chunks
            const uint32_t a0 = f2h2(s[2 * t][0], s[2 * t][1]);
            const uint32_t a1 = f2h2(s[2 * t][2], s[2 * t][3]);
            const uint32_t a2 = f2h2(s[2 * t + 1][0], s[2 * t + 1][1]);
            const uint32_t a3 = f2h2(s[2 * t + 1][2], s[2 * t + 1][3]);
#pragma unroll
            for (int nb = 0; nb < 8; nb++) {
                const uint32_t* vp = sVT + (nb * 8 + g) * STRVT2 + t * 8 + tig;
                mma_f16(o[nb], a0, a1, a2, a3, vp[0], vp[4]);
            }
        }
    }

    // ---- finalize -----------------------------------------------------------
    const float inv0 = 1.f / l0;
    const float inv1 = 1.f / l1;
    float* Og = O + (size_t)bn * kT * kD;
#pragma unroll
    for (int nb = 0; nb < 8; nb++) {
        *(float2*)(Og + (size_t)rowg0 * kD + nb * 8 + 2 * tig) =
            make_float2(o[nb][0] * inv0, o[nb][1] * inv0);
        *(float2*)(Og + (size_t)rowg1 * kD + nb * 8 + 2 * tig) =
            make_float2(o[nb][2] * inv1, o[nb][3] * inv1);
    }
}

extern "C" void kernel_launch(void* const* d_in, const int* in_sizes, int n_in,
                              void* d_out, int out_size) {
    const float* q = (const float*)d_in[0];
    const float* k = (const float*)d_in[1];
    const float* v = (const float*)d_in[2];
    float* o = (float*)d_out;

    const size_t smem_bytes = (size_t)SMEM_WORDS * sizeof(float);
    cudaFuncSetAttribute(attn_mixed_v2_kernel,
                         cudaFuncAttributeMaxDynamicSharedMemorySize,
                         (int)smem_bytes);

    dim3 grid(kT / BM, 64);
    attn_mixed_v2_kernel<<<grid, THREADS, smem_bytes>>>(q, k, v, o);
}

// round 7
// speedup vs baseline: 1.3698x; 1.3698x over previous
#include <cuda_runtime.h>
#include <cuda_fp16.h>
#include <math.h>
#include <stdint.h>

// ----------------------------------------------------------------------------
// Causal masked softmax attention. N=64, T=1024, D=64.
// BM=128 queries/block (8 warps), BN=64 key tiles.
// QK^T: tf32 m16n8k8, Q fragments register-resident.
// PV:   fp16 m16n8k16, P in registers (tf32-C == fp16-A layout),
//       V stored row-major fp16 in smem, B fragments via ldmatrix.x4.trans
//       (conflict-free; replaces the 8-way-conflicted transpose store of v2).
// ----------------------------------------------------------------------------

namespace {
constexpr int kT = 1024;
constexpr int BM = 128;
constexpr int BN = 64;
constexpr int kD = 64;
constexpr int THREADS = 256;
constexpr int STRK = 68;     // sK float stride: S-mma B-load bank (4g+tig) bijective
constexpr int STRVH = 72;    // sV half stride (36 words; rows 16B-aligned, 144B apart)
constexpr float kQScale = 0.18033688011112042f;  // (1/8) * log2(e)
constexpr float kPad = -1e30f;                   // exp2 -> exactly 0
constexpr int SM_K = 0;                          // word offsets
constexpr int SM_V = BN * STRK;                  // 4352
constexpr int SM_F = SM_V + BN * (STRVH / 2);    // 4352 + 2304 = 6656
constexpr int SMEM_WORDS = SM_F + BN;            // 6720 words = 26.25 KB
}  // namespace

__device__ __forceinline__ float ex2f(float x) {
    float r; asm("ex2.approx.ftz.f32 %0, %1;" : "=f"(r) : "f"(x)); return r;
}
__device__ __forceinline__ float tf32r(float x) {
    uint32_t u; asm("cvt.rna.tf32.f32 %0, %1;" : "=r"(u) : "f"(x));
    return __uint_as_float(u);
}
__device__ __forceinline__ uint32_t f2h2(float lo, float hi) {
    __half2 h = __floats2half2_rn(lo, hi);
    return *reinterpret_cast<uint32_t*>(&h);
}
__device__ __forceinline__ void mma_tf32(float (&d)[4],
                                         uint32_t a0, uint32_t a1,
                                         uint32_t a2, uint32_t a3,
                                         uint32_t b0, uint32_t b1) {
    asm volatile(
        "mma.sync.aligned.m16n8k8.row.col.f32.tf32.tf32.f32 "
        "{%0,%1,%2,%3}, {%4,%5,%6,%7}, {%8,%9}, {%0,%1,%2,%3};\n"
        : "+f"(d[0]), "+f"(d[1]), "+f"(d[2]), "+f"(d[3])
        : "r"(a0), "r"(a1), "r"(a2), "r"(a3), "r"(b0), "r"(b1));
}
__device__ __forceinline__ void mma_f16(float (&d)[4],
                                        uint32_t a0, uint32_t a1,
                                        uint32_t a2, uint32_t a3,
                                        uint32_t b0, uint32_t b1) {
    asm volatile(
        "mma.sync.aligned.m16n8k16.row.col.f32.f16.f16.f32 "
        "{%0,%1,%2,%3}, {%4,%5,%6,%7}, {%8,%9}, {%0,%1,%2,%3};\n"
        : "+f"(d[0]), "+f"(d[1]), "+f"(d[2]), "+f"(d[3])
        : "r"(a0), "r"(a1), "r"(a2), "r"(a3), "r"(b0), "r"(b1));
}
__device__ __forceinline__ void ldsm_x4_trans(uint32_t& r0, uint32_t& r1,
                                              uint32_t& r2, uint32_t& r3,
                                              uint32_t addr) {
    asm volatile(
        "ldmatrix.sync.aligned.m8n8.x4.trans.shared.b16 {%0,%1,%2,%3}, [%4];\n"
        : "=r"(r0), "=r"(r1), "=r"(r2), "=r"(r3) : "r"(addr));
}

__global__ __launch_bounds__(THREADS, 2)
void attn_bm128_kernel(const float* __restrict__ Q, const float* __restrict__ K,
                       const float* __restrict__ V, float* __restrict__ O) {
    extern __shared__ float sm[];
    float* sK = sm + SM_K;                     // [BN][STRK] tf32 keys
    uint32_t* sV2 = (uint32_t*)(sm + SM_V);    // [BN][36] fp16 V rows (half2)
    float* sF = sm + SM_F;                     // [BN] |K| row sums

    const int tid = threadIdx.x;
    const int warp = tid >> 5;   // 0..7
    const int lane = tid & 31;
    const int g = lane >> 2;     // 0..7
    const int tig = lane & 3;    // 0..3
    const int qt = (kT / BM - 1) - blockIdx.x;   // heavy q-tiles first
    const int bn = blockIdx.y;
    const int q0 = qt * BM;

    const float* Qg = Q + ((size_t)bn * kT + q0) * kD;
    const float* Kg = K + (size_t)bn * kT * kD;
    const float* Vg = V + (size_t)bn * kT * kD;

    const int tx = tid & 15, ty = tid >> 4;      // 16x16 loader layout

    // ---- stage Q (scaled, tf32) through sK in two 64-row passes -------------
    uint32_t qf[8][4];
#pragma unroll
    for (int p = 0; p < 2; p++) {
        if (p) __syncthreads();                  // pass-0 qf reads done
#pragma unroll
        for (int i = 0; i < 4; i++) {
            const int r = ty + 16 * i;           // 0..63
            float4 qv = *(const float4*)(Qg + (size_t)(64 * p + r) * kD + 4 * tx);
            *(float4*)(sK + r * STRK + 4 * tx) =
                make_float4(tf32r(qv.x * kQScale), tf32r(qv.y * kQScale),
                            tf32r(qv.z * kQScale), tf32r(qv.w * kQScale));
        }
        __syncthreads();
        if ((warp >> 2) == p) {                  // warps 0-3 pass0, 4-7 pass1
            const float* mq = sK + ((warp & 3) * 16) * STRK;
#pragma unroll
            for (int kb = 0; kb < 8; kb++) {
                qf[kb][0] = __float_as_uint(mq[g * STRK + kb * 8 + tig]);
                qf[kb][1] = __float_as_uint(mq[(g + 8) * STRK + kb * 8 + tig]);
                qf[kb][2] = __float_as_uint(mq[g * STRK + kb * 8 + tig + 4]);
                qf[kb][3] = __float_as_uint(mq[(g + 8) * STRK + kb * 8 + tig + 4]);
            }
        }
    }

    float m0 = kPad, m1 = kPad, l0 = 0.f, l1 = 0.f;
    float o[8][4];
#pragma unroll
    for (int nb = 0; nb < 8; nb++)
#pragma unroll
        for (int j = 0; j < 4; j++) o[nb][j] = 0.f;

    const int rowg0 = q0 + warp * 16 + g;
    const int rowg1 = rowg0 + 8;
    const uint32_t vbase =
        (uint32_t)__cvta_generic_to_shared(sV2);   // byte addr of V region
    const uint32_t lrow = lane & 15, lhi = lane >> 4;  // ldmatrix lane roles

    const int nkt = 2 * qt + 2;                  // key tiles (keys <= q0+127)
    for (int kt = 0; kt < nkt; kt++) {
        const int k0 = kt * BN;
        __syncthreads();   // prior tile's MMAs done with sK/sV2 (+ qf pass-1)

        // ---- load K (tf32) + flags, V (fp16 row-major) ----------------------
#pragma unroll
        for (int i = 0; i < 4; i++) {
            const int r = ty + 16 * i;           // 0..63
            float4 kv = *(const float4*)(Kg + (size_t)(k0 + r) * kD + 4 * tx);
            *(float4*)(sK + r * STRK + 4 * tx) =
                make_float4(tf32r(kv.x), tf32r(kv.y), tf32r(kv.z), tf32r(kv.w));
            float asum = fabsf(kv.x) + fabsf(kv.y) + fabsf(kv.z) + fabsf(kv.w);
#pragma unroll
            for (int off = 8; off > 0; off >>= 1)
                asum += __shfl_xor_sync(0xffffffffu, asum, off, 16);
            if (tx == 0) sF[r] = asum;
            float4 vv = *(const float4*)(Vg + (size_t)(k0 + r) * kD + 4 * tx);
            *(uint2*)(sV2 + r * (STRVH / 2) + 2 * tx) =
                make_uint2(f2h2(vv.x, vv.y), f2h2(vv.z, vv.w));
        }
        __syncthreads();

        // warps whose rows all precede this key tile: masked to zero anyway
        if (k0 > q0 + warp * 16 + 15) continue;  // barriers are outside this

        // ---- S = Q K^T (tf32 tensor cores) ----------------------------------
        float s[8][4];
#pragma unroll
        for (int nb = 0; nb < 8; nb++)
#pragma unroll
            for (int j = 0; j < 4; j++) s[nb][j] = 0.f;
#pragma unroll
        for (int kb = 0; kb < 8; kb++) {
#pragma unroll
            for (int nb = 0; nb < 8; nb++) {
                const float* kp = sK + (nb * 8 + g) * STRK + kb * 8 + tig;
                mma_tf32(s[nb], qf[kb][0], qf[kb][1], qf[kb][2], qf[kb][3],
                         __float_as_uint(kp[0]), __float_as_uint(kp[4]));
            }
        }

        // ---- masks ----------------------------------------------------------
        const bool needC = (k0 + BN - 1 > q0 + warp * 16);  // future keys exist
#pragma unroll
        for (int nb = 0; nb < 8; nb++) {
            const int c = k0 + nb * 8 + 2 * tig;
            const float f0 = sF[nb * 8 + 2 * tig];
            const float f1 = sF[nb * 8 + 2 * tig + 1];
            if (f0 == 0.f) { s[nb][0] = kPad; s[nb][2] = kPad; }
            if (f1 == 0.f) { s[nb][1] = kPad; s[nb][3] = kPad; }
            if (needC) {
                if (c > rowg0)     s[nb][0] = kPad;
                if (c + 1 > rowg0) s[nb][1] = kPad;
                if (c > rowg1)     s[nb][2] = kPad;
                if (c + 1 > rowg1) s[nb][3] = kPad;
            }
        }

        // ---- online softmax (base 2), P kept in registers -------------------
        float rmax0 = kPad, rmax1 = kPad;
#pragma unroll
        for (int nb = 0; nb < 8; nb++) {
            rmax0 = fmaxf(rmax0, fmaxf(s[nb][0], s[nb][1]));
            rmax1 = fmaxf(rmax1, fmaxf(s[nb][2], s[nb][3]));
        }
        rmax0 = fmaxf(rmax0, __shfl_xor_sync(0xffffffffu, rmax0, 1));
        rmax0 = fmaxf(rmax0, __shfl_xor_sync(0xffffffffu, rmax0, 2));
        rmax1 = fmaxf(rmax1, __shfl_xor_sync(0xffffffffu, rmax1, 1));
        rmax1 = fmaxf(rmax1, __shfl_xor_sync(0xffffffffu, rmax1, 2));
        const float mn0 = fmaxf(m0, rmax0);
        const float mn1 = fmaxf(m1, rmax1);
        const float corr0 = ex2f(m0 - mn0);
        const float corr1 = ex2f(m1 - mn1);
        float rs0 = 0.f, rs1 = 0.f;
#pragma unroll
        for (int nb = 0; nb < 8; nb++) {
            s[nb][0] = ex2f(s[nb][0] - mn0);
            s[nb][1] = ex2f(s[nb][1] - mn0);
            s[nb][2] = ex2f(s[nb][2] - mn1);
            s[nb][3] = ex2f(s[nb][3] - mn1);
            rs0 += s[nb][0] + s[nb][1];
            rs1 += s[nb][2] + s[nb][3];
        }
        rs0 += __shfl_xor_sync(0xffffffffu, rs0, 1);
        rs0 += __shfl_xor_sync(0xffffffffu, rs0, 2);
        rs1 += __shfl_xor_sync(0xffffffffu, rs1, 1);
        rs1 += __shfl_xor_sync(0xffffffffu, rs1, 2);
        l0 = l0 * corr0 + rs0; m0 = mn0;
        l1 = l1 * corr1 + rs1; m1 = mn1;
#pragma unroll
        for (int nb = 0; nb < 8; nb++) {
            o[nb][0] *= corr0; o[nb][1] *= corr0;
            o[nb][2] *= corr1; o[nb][3] *= corr1;
        }

        // ---- O += P V (fp16; B fragments via ldmatrix.x4.trans) -------------
#pragma unroll
        for (int t = 0; t < 4; t++) {            // 16-key chunks
            const uint32_t a0 = f2h2(s[2 * t][0], s[2 * t][1]);
            const uint32_t a1 = f2h2(s[2 * t][2], s[2 * t][3]);
            const uint32_t a2 = f2h2(s[2 * t + 1][0], s[2 * t + 1][1]);
            const uint32_t a3 = f2h2(s[2 * t + 1][2], s[2 * t + 1][3]);
            // lane -> row of one 8x8 tile: keys 16t+lrow, dims 8*lhi (+16 per nbp)
            const uint32_t addr0 =
                vbase + ((16 * t + lrow) * STRVH + 8 * lhi) * 2;
#pragma unroll
            for (int nbp = 0; nbp < 4; nbp++) {  // dim-octet pairs
                uint32_t b0, b1, b2, b3;
                ldsm_x4_trans(b0, b1, b2, b3, addr0 + nbp * 32);
                mma_f16(o[2 * nbp], a0, a1, a2, a3, b0, b1);
                mma_f16(o[2 * nbp + 1], a0, a1, a2, a3, b2, b3);
            }
        }
    }

    // ---- finalize -----------------------------------------------------------
    const float inv0 = 1.f / l0;
    const float inv1 = 1.f / l1;
    float* Og = O + (size_t)bn * kT * kD;
#pragma unroll
    for (int nb = 0; nb < 8; nb++) {
        *(float2*)(Og + (size_t)rowg0 * kD + nb * 8 + 2 * tig) =
            make_float2(o[nb][0] * inv0, o[nb][1] * inv0);
        *(float2*)(Og + (size_t)rowg1 * kD + nb * 8 + 2 * tig) =
            make_float2(o[nb][2] * inv1, o[nb][3] * inv1);
    }
}

extern "C" void kernel_launch(void* const* d_in, const int* in_sizes, int n_in,
                              void* d_out, int out_size) {
    const float* q = (const float*)d_in[0];
    const float* k = (const float*)d_in[1];
    const float* v = (const float*)d_in[2];
    float* o = (float*)d_out;

    const size_t smem_bytes = (size_t)SMEM_WORDS * sizeof(float);  // 26.25 KB
    cudaFuncSetAttribute(attn_bm128_kernel,
                         cudaFuncAttributeMaxDynamicSharedMemorySize,
                         (int)smem_bytes);

    dim3 grid(kT / BM, 64);   // 8 q-tiles x 64 batch-heads = 512 blocks
    attn_bm128_kernel<<<grid, THREADS, smem_bytes>>>(q, k, v, o);
}